// round 1
// baseline (speedup 1.0000x reference)
#include <cuda_runtime.h>
#include <cstdint>

#define M_ROWS 8192
#define IN_F   512
#define OUT_F  512
#define NBAS   11
#define KDIM   (IN_F * 12)     // 6144
#define BK     16
#define NKT    (KDIM / BK)     // 384
#define SSTRIDE 20             // 16 + 4 pad; 20 floats = 80B = 16B-aligned rows

// Scratch (allocation-free rule: __device__ globals)
__device__ float g_E[(size_t)M_ROWS * KDIM];   // expanded [x_i, basis_0..10] per feature
__device__ float g_W[(size_t)OUT_F * KDIM];    // packed [Wb, Ws_0..10] per (o,i)

__device__ __forceinline__ float to_tf32(float x) {
    uint32_t u;
    asm("cvt.rna.tf32.f32 %0, %1;" : "=r"(u) : "f"(x));
    return __uint_as_float(u);
}

// ---------------------------------------------------------------------------
// Kernel 1: expand x -> E.  One thread per (b, i) element.
// Cox-de Boor recursion over the fixed uniform grid, fully constant-folded.
// ---------------------------------------------------------------------------
__global__ void expand_kernel(const float* __restrict__ x, int total) {
    int idx = blockIdx.x * blockDim.x + threadIdx.x;
    if (idx >= total) return;
    float xv = x[idx];
    float xc = fminf(fmaxf(xv, -2.0f), 2.0f);

    const float h = 2.0f / 14.0f;
    float g[15];
#pragma unroll
    for (int i = 0; i < 15; i++) g[i] = -1.0f + h * (float)i;

    float b[14];
#pragma unroll
    for (int s = 0; s < 14; s++)
        b[s] = (xc >= g[s] && xc < g[s + 1]) ? 1.0f : 0.0f;

#pragma unroll
    for (int k = 1; k <= 3; k++) {
#pragma unroll
        for (int s = 0; s < 14 - k; s++) {
            float r1 = 1.0f / (g[s + k] - g[s]);          // constant-folded
            float r2 = 1.0f / (g[s + k + 1] - g[s + 1]);  // constant-folded
            b[s] = (xc - g[s]) * r1 * b[s] + (g[s + k + 1] - xc) * r2 * b[s + 1];
        }
    }

    float o[12];
    o[0] = to_tf32(xv);                 // base path uses UNclipped x
#pragma unroll
    for (int j = 0; j < NBAS; j++) o[1 + j] = to_tf32(b[j]);

    // idx = b*IN_F + i  ->  E[b][i*12 .. i*12+11]  ==  g_E + idx*12
    float4* dst = reinterpret_cast<float4*>(g_E + (size_t)idx * 12);
    dst[0] = make_float4(o[0], o[1], o[2],  o[3]);
    dst[1] = make_float4(o[4], o[5], o[6],  o[7]);
    dst[2] = make_float4(o[8], o[9], o[10], o[11]);
}

// ---------------------------------------------------------------------------
// Kernel 2: pack [base_weight | spline_weight] -> W (OUT_F x KDIM, K-major)
// ---------------------------------------------------------------------------
__global__ void pack_kernel(const float* __restrict__ bw, const float* __restrict__ sw) {
    int idx = blockIdx.x * blockDim.x + threadIdx.x;     // over OUT_F*IN_F
    if (idx >= OUT_F * IN_F) return;
    // (o*IN_F + i)*12 == o*KDIM + i*12
    float* dst = g_W + (size_t)idx * 12;
    dst[0] = to_tf32(bw[idx]);
    const float* s = sw + (size_t)idx * NBAS;
#pragma unroll
    for (int j = 0; j < NBAS; j++) dst[1 + j] = to_tf32(s[j]);
}

// ---------------------------------------------------------------------------
// Kernel 3: GEMM  C[M,N] = E[M,K] * W[N,K]^T   (tf32 mma.sync, fp32 accum)
// CTA tile 128x128x16, 8 warps (2x4), warp tile 64x32, double-buffered cp.async
// ---------------------------------------------------------------------------
__device__ __forceinline__ void cp_async16(uint32_t saddr, const void* gptr) {
    asm volatile("cp.async.cg.shared.global [%0], [%1], 16;\n" :: "r"(saddr), "l"(gptr));
}

__device__ __forceinline__ void load_tile(uint32_t sA_base, uint32_t sB_base,
                                          const float* Ab, const float* Bb,
                                          int buf, int kt, int tid) {
    int bk = kt * BK;
#pragma unroll
    for (int r = 0; r < 2; r++) {
        int q   = tid + r * 256;        // 512 float4 per operand tile
        int row = q >> 2;
        int c4  = (q & 3) * 4;
        uint32_t so = (uint32_t)((buf * 128 * SSTRIDE + row * SSTRIDE + c4) * 4);
        cp_async16(sA_base + so, Ab + (size_t)row * KDIM + bk + c4);
        cp_async16(sB_base + so, Bb + (size_t)row * KDIM + bk + c4);
    }
    asm volatile("cp.async.commit_group;\n");
}

__global__ void __launch_bounds__(256, 2) gemm_kernel(float* __restrict__ C) {
    __shared__ float sA[2][128 * SSTRIDE];
    __shared__ float sB[2][128 * SSTRIDE];

    const int tid  = threadIdx.x;
    const int lane = tid & 31;
    const int warp = tid >> 5;
    const int m0 = (warp >> 2) * 64;
    const int n0 = (warp & 3) * 32;

    const float* Ab = g_E + (size_t)blockIdx.y * 128 * KDIM;
    const float* Bb = g_W + (size_t)blockIdx.x * 128 * KDIM;

    float acc[4][4][4];
#pragma unroll
    for (int i = 0; i < 4; i++)
#pragma unroll
        for (int j = 0; j < 4; j++)
#pragma unroll
            for (int k = 0; k < 4; k++) acc[i][j][k] = 0.0f;

    uint32_t sA_base = (uint32_t)__cvta_generic_to_shared(&sA[0][0]);
    uint32_t sB_base = (uint32_t)__cvta_generic_to_shared(&sB[0][0]);

    load_tile(sA_base, sB_base, Ab, Bb, 0, 0, tid);

#pragma unroll 1
    for (int kt = 0; kt < NKT; kt++) {
        asm volatile("cp.async.wait_group 0;\n");
        __syncthreads();
        const int cur = kt & 1;
        if (kt + 1 < NKT) load_tile(sA_base, sB_base, Ab, Bb, cur ^ 1, kt + 1, tid);

        const float* a   = &sA[cur][0];
        const float* bsh = &sB[cur][0];

#pragma unroll
        for (int ks = 0; ks < 2; ks++) {
            uint32_t af[4][4], bf[4][2];
            const int kc = ks * 8 + (lane & 3);
#pragma unroll
            for (int mi = 0; mi < 4; mi++) {
                int r = m0 + mi * 16 + (lane >> 2);
                af[mi][0] = __float_as_uint(a[r * SSTRIDE + kc]);
                af[mi][1] = __float_as_uint(a[(r + 8) * SSTRIDE + kc]);
                af[mi][2] = __float_as_uint(a[r * SSTRIDE + kc + 4]);
                af[mi][3] = __float_as_uint(a[(r + 8) * SSTRIDE + kc + 4]);
            }
#pragma unroll
            for (int ni = 0; ni < 4; ni++) {
                int r = n0 + ni * 8 + (lane >> 2);
                bf[ni][0] = __float_as_uint(bsh[r * SSTRIDE + kc]);
                bf[ni][1] = __float_as_uint(bsh[r * SSTRIDE + kc + 4]);
            }
#pragma unroll
            for (int mi = 0; mi < 4; mi++)
#pragma unroll
                for (int ni = 0; ni < 4; ni++)
                    asm volatile(
                        "mma.sync.aligned.m16n8k8.row.col.f32.tf32.tf32.f32 "
                        "{%0,%1,%2,%3}, {%4,%5,%6,%7}, {%8,%9}, {%0,%1,%2,%3};\n"
                        : "+f"(acc[mi][ni][0]), "+f"(acc[mi][ni][1]),
                          "+f"(acc[mi][ni][2]), "+f"(acc[mi][ni][3])
                        : "r"(af[mi][0]), "r"(af[mi][1]), "r"(af[mi][2]), "r"(af[mi][3]),
                          "r"(bf[ni][0]), "r"(bf[ni][1]));
        }
    }

    // Epilogue: fp32 writes, float2 per fragment row
    float* Cb = C + (size_t)blockIdx.y * 128 * OUT_F + blockIdx.x * 128;
#pragma unroll
    for (int mi = 0; mi < 4; mi++) {
#pragma unroll
        for (int ni = 0; ni < 4; ni++) {
            int r = m0 + mi * 16 + (lane >> 2);
            int c = n0 + ni * 8 + ((lane & 3) << 1);
            float2 v0 = make_float2(acc[mi][ni][0], acc[mi][ni][1]);
            float2 v1 = make_float2(acc[mi][ni][2], acc[mi][ni][3]);
            *reinterpret_cast<float2*>(Cb + (size_t)r * OUT_F + c)       = v0;
            *reinterpret_cast<float2*>(Cb + (size_t)(r + 8) * OUT_F + c) = v1;
        }
    }
}

// ---------------------------------------------------------------------------
extern "C" void kernel_launch(void* const* d_in, const int* in_sizes, int n_in,
                              void* d_out, int out_size) {
    const float* x  = (const float*)d_in[0];   // (8192, 512)
    const float* bw = (const float*)d_in[1];   // (512, 512)
    const float* sw = (const float*)d_in[2];   // (512, 512, 11)
    float* out = (float*)d_out;                // (8192, 512)

    int total = in_sizes[0];                   // 8192*512
    expand_kernel<<<(total + 255) / 256, 256>>>(x, total);
    pack_kernel<<<(OUT_F * IN_F + 255) / 256, 256>>>(bw, sw);
    gemm_kernel<<<dim3(OUT_F / 128, M_ROWS / 128), 256>>>(out);
}

// round 5
// speedup vs baseline: 1.4390x; 1.4390x over previous
#include <cuda_runtime.h>
#include <cstdint>

#define M_ROWS 8192
#define IN_F   512
#define OUT_F  512
#define NBAS   11
#define KDIM   6144                 // 512 * 12
#define BK     32
#define NKT    (KDIM / BK)          // 192
#define A_TILE_B 16384              // 128*32*4
#define B_TILE_B 16384
#define STAGE_B  (A_TILE_B + B_TILE_B)
#define NSTAGE   3
#define GEMM_SMEM (NSTAGE * STAGE_B)   // 98304
#define MBLK_FLTS (128 * KDIM)      // 786432 floats per 128-row block

__device__ float g_E[(size_t)M_ROWS * KDIM];   // A, fragment-permuted
__device__ float g_W[(size_t)OUT_F * KDIM];    // B, fragment-permuted

__device__ __forceinline__ float to_tf32(float x) {
    uint32_t u;
    asm("cvt.rna.tf32.f32 %0, %1;" : "=r"(u) : "f"(x));
    return __uint_as_float(u);
}
__device__ __forceinline__ void cp_async16(uint32_t saddr, const void* g) {
    asm volatile("cp.async.cg.shared.global [%0], [%1], 16;\n" :: "r"(saddr), "l"(g));
}

// Permuted A offset within a (128 x 6144) block, for element (row bl in [0,128), k)
// tile kt=k>>5; unit u = (bl>>4)*4 + ((k>>3)&3); lane=((bl&7)<<2)|(k&3);
// slot = ((bl>>3)&1) + 2*((k>>2)&1)
__device__ __forceinline__ int a_perm_off(int bl, int k) {
    int kt = k >> 5, kk = k & 31;
    int u = ((bl >> 4) << 2) | (kk >> 3);
    int lane = ((bl & 7) << 2) | (kk & 3);
    int slot = ((bl >> 3) & 1) | (((kk >> 2) & 1) << 1);
    return kt * 4096 + u * 128 + lane * 4 + slot;
}
// Permuted B offset within a (128 x 6144) block, element (row ol in [0,128), k)
__device__ __forceinline__ int b_perm_off(int ol, int k) {
    int kt = k >> 5, kk = k & 31;
    int u = ((ol >> 3) << 2) | (kk >> 3);
    int lane = ((ol & 7) << 2) | (kk & 3);
    int slot = (kk >> 2) & 1;
    return kt * 4096 + u * 64 + lane * 2 + slot;
}

// ---------------------------------------------------------------------------
// Kernel 1: expand x -> E (fragment-permuted). Block = 128 rows x 8 features
// (96 k-cols = exactly 3 tiles of BK=32). 256 threads, 4 (b,i) pairs each.
// ---------------------------------------------------------------------------
__global__ void expand_kernel(const float* __restrict__ x) {
    __shared__ float st[12288];                  // 3 tiles * 4096 floats
    const int t  = threadIdx.x;
    const int mb = blockIdx.x >> 6;              // 64 row-blocks
    const int gg = blockIdx.x & 63;              // 64 groups of 8 features

    const float h = 2.0f / 14.0f;
    float g[15];
#pragma unroll
    for (int i = 0; i < 15; i++) g[i] = -1.0f + h * (float)i;

#pragma unroll
    for (int p = 0; p < 4; p++) {
        int q = p * 256 + t;                     // 0..1023
        int bl = q >> 3;                         // row in block
        int il = q & 7;                          // feature in group
        float xv = x[(size_t)(mb * 128 + bl) * IN_F + gg * 8 + il];
        float xc = fminf(fmaxf(xv, -2.0f), 2.0f);

        float b[14];
#pragma unroll
        for (int s = 0; s < 14; s++) b[s] = (xc >= g[s] && xc < g[s + 1]) ? 1.0f : 0.0f;
#pragma unroll
        for (int k = 1; k <= 3; k++)
#pragma unroll
            for (int s = 0; s < 14 - k; s++) {
                float r1 = 1.0f / (g[s + k] - g[s]);
                float r2 = 1.0f / (g[s + k + 1] - g[s + 1]);
                b[s] = (xc - g[s]) * r1 * b[s] + (g[s + k + 1] - xc) * r2 * b[s + 1];
            }

        int kbase = il * 12;
        st[a_perm_off(bl, kbase)] = to_tf32(xv);
#pragma unroll
        for (int j = 0; j < NBAS; j++)
            st[a_perm_off(bl, kbase + 1 + j)] = to_tf32(b[j]);
    }
    __syncthreads();

    float4* dst = reinterpret_cast<float4*>(g_E + (size_t)mb * MBLK_FLTS + gg * 12288);
    const float4* src = reinterpret_cast<const float4*>(st);
#pragma unroll
    for (int r = 0; r < 12; r++) dst[t + r * 256] = src[t + r * 256];
}

// ---------------------------------------------------------------------------
// Kernel 2: pack weights -> W (fragment-permuted)
// ---------------------------------------------------------------------------
__global__ void pack_kernel(const float* __restrict__ bw, const float* __restrict__ sw) {
    int idx = blockIdx.x * blockDim.x + threadIdx.x;   // over OUT_F*IN_F
    if (idx >= OUT_F * IN_F) return;
    int o = idx >> 9, i = idx & 511;
    float* base = g_W + (size_t)(o >> 7) * MBLK_FLTS;
    int ol = o & 127;
    int kbase = i * 12;
    base[b_perm_off(ol, kbase)] = to_tf32(bw[idx]);
    const float* s = sw + (size_t)idx * NBAS;
#pragma unroll
    for (int j = 0; j < NBAS; j++)
        base[b_perm_off(ol, kbase + 1 + j)] = to_tf32(s[j]);
}

// ---------------------------------------------------------------------------
// Kernel 3: tf32 mma.sync GEMM, fragment-permuted operands.
// CTA 128x128, 8 warps (2x4), warp 64x32, BK=32, 3-stage cp.async.
// ---------------------------------------------------------------------------
__global__ void __launch_bounds__(256, 2) gemm_kernel(float* __restrict__ C) {
    extern __shared__ char dsm[];
    const int tid  = threadIdx.x;
    const int lane = tid & 31;
    const int wid  = tid >> 5;
    const int mwarp = wid >> 2;        // 0..1
    const int nwarp = wid & 3;         // 0..3

    const float* Ab = g_E + (size_t)blockIdx.y * MBLK_FLTS;
    const float* Bb = g_W + (size_t)blockIdx.x * MBLK_FLTS;
    uint32_t sbase;
    asm("{ .reg .u64 t; cvta.to.shared.u64 t, %1; cvt.u32.u64 %0, t; }" : "=r"(sbase) : "l"(dsm));

    float acc[4][4][4];
#pragma unroll
    for (int i = 0; i < 4; i++)
#pragma unroll
        for (int j = 0; j < 4; j++)
#pragma unroll
            for (int k = 0; k < 4; k++) acc[i][j][k] = 0.0f;

    // ---- tile loader: stage s <- tile kt (A 16KB + B 16KB, contiguous) ----
    auto load_tile = [&](int kt, int s) {
        uint32_t sd = sbase + s * STAGE_B;
        const float* ga = Ab + (size_t)kt * 4096;
        const float* gb = Bb + (size_t)kt * 4096;
#pragma unroll
        for (int r = 0; r < 4; r++) {
            int q = tid + r * 256;                     // 0..1023 float4 chunks
            cp_async16(sd + q * 16, ga + q * 4);
            cp_async16(sd + A_TILE_B + q * 16, gb + q * 4);
        }
        asm volatile("cp.async.commit_group;\n");
    };

    load_tile(0, 0);
    load_tile(1, 1);

    int bufc = 0, bufl = 2;
#pragma unroll 1
    for (int kt = 0; kt < NKT; kt++) {
        asm volatile("cp.async.wait_group 1;\n" ::: "memory");
        __syncthreads();

        if (kt + 2 < NKT) load_tile(kt + 2, bufl);
        else asm volatile("cp.async.commit_group;\n");

        const char* sa = dsm + bufc * STAGE_B;
        const char* sb = sa + A_TILE_B;

#pragma unroll
        for (int kq = 0; kq < 4; kq++) {
            float4 af[4];
            float2 bf[4];
#pragma unroll
            for (int mi = 0; mi < 4; mi++)
                af[mi] = *reinterpret_cast<const float4*>(
                    sa + ((((mwarp * 4 + mi) * 4 + kq) * 32 + lane) << 4));
#pragma unroll
            for (int ni = 0; ni < 4; ni++)
                bf[ni] = *reinterpret_cast<const float2*>(
                    sb + ((((nwarp * 4 + ni) * 4 + kq) * 32 + lane) << 3));
#pragma unroll
            for (int mi = 0; mi < 4; mi++)
#pragma unroll
                for (int ni = 0; ni < 4; ni++)
                    asm volatile(
                        "mma.sync.aligned.m16n8k8.row.col.f32.tf32.tf32.f32 "
                        "{%0,%1,%2,%3}, {%4,%5,%6,%7}, {%8,%9}, {%0,%1,%2,%3};\n"
                        : "+f"(acc[mi][ni][0]), "+f"(acc[mi][ni][1]),
                          "+f"(acc[mi][ni][2]), "+f"(acc[mi][ni][3])
                        : "r"(__float_as_uint(af[mi].x)), "r"(__float_as_uint(af[mi].y)),
                          "r"(__float_as_uint(af[mi].z)), "r"(__float_as_uint(af[mi].w)),
                          "r"(__float_as_uint(bf[ni].x)), "r"(__float_as_uint(bf[ni].y)));
        }

        bufc = (bufc == 2) ? 0 : bufc + 1;
        bufl = (bufl == 2) ? 0 : bufl + 1;
    }

    // ---- epilogue ----
    float* Cb = C + (size_t)blockIdx.y * 128 * OUT_F + blockIdx.x * 128;
    const int m0 = mwarp * 64, n0 = nwarp * 32;
#pragma unroll
    for (int mi = 0; mi < 4; mi++) {
#pragma unroll
        for (int ni = 0; ni < 4; ni++) {
            int r = m0 + mi * 16 + (lane >> 2);
            int c = n0 + ni * 8 + ((lane & 3) << 1);
            *reinterpret_cast<float2*>(Cb + (size_t)r * OUT_F + c) =
                make_float2(acc[mi][ni][0], acc[mi][ni][1]);
            *reinterpret_cast<float2*>(Cb + (size_t)(r + 8) * OUT_F + c) =
                make_float2(acc[mi][ni][2], acc[mi][ni][3]);
        }
    }
}

// ---------------------------------------------------------------------------
extern "C" void kernel_launch(void* const* d_in, const int* in_sizes, int n_in,
                              void* d_out, int out_size) {
    const float* x  = (const float*)d_in[0];   // (8192, 512)
    const float* bw = (const float*)d_in[1];   // (512, 512)
    const float* sw = (const float*)d_in[2];   // (512, 512, 11)
    float* out = (float*)d_out;                // (8192, 512)

    cudaFuncSetAttribute(gemm_kernel,
                         cudaFuncAttributeMaxDynamicSharedMemorySize, GEMM_SMEM);

    expand_kernel<<<64 * 64, 256>>>(x);
    pack_kernel<<<(OUT_F * IN_F + 255) / 256, 256>>>(bw, sw);
    gemm_kernel<<<dim3(OUT_F / 128, M_ROWS / 128), 256, GEMM_SMEM>>>(out);
}

// round 11
// speedup vs baseline: 2.6120x; 1.8151x over previous
#include <cuda_runtime.h>
#include <cuda_fp16.h>
#include <cstdint>

#define M_ROWS 8192
#define IN_F   512
#define OUT_F  512
#define NBAS   11
#define KDIM   6144                 // 512 * 12
#define BK     64
#define NKT    (KDIM / BK)          // 96
#define TILE_HALVES 8192            // 128 * 64
#define TILE_B  16384               // bytes per operand tile (fp16)
#define STAGE_B (2 * TILE_B)        // 32768
#define NSTAGE  3
#define GEMM_SMEM (NSTAGE * STAGE_B)   // 98304
#define MBLK_HALVES (128 * KDIM)    // 786432 halves per 128-row block

__device__ __half g_E[(size_t)M_ROWS * KDIM];   // A, m16n8k16-fragment-permuted
__device__ __half g_W[(size_t)OUT_F * KDIM];    // B, fragment-permuted

__device__ __forceinline__ void cp_async16(uint32_t saddr, const void* g) {
    asm volatile("cp.async.cg.shared.global [%0], [%1], 16;\n" :: "r"(saddr), "l"(g));
}

// half2-granule offset of element pair (row, k0) [k0 even] inside one 128x64 tile
// A (16x16 fragments): unit = (row>>4)*4 + (k64>>4); lane=((row&7)<<2)|((kk>>1)&3);
//   reg = ((row>>3)&1) | ((kk>>3)<<1);  h2 = unit*128 + lane*4 + reg
__device__ __forceinline__ int a_h2(int row, int k64) {
    int kk = k64 & 15;
    int unit = ((row >> 4) << 2) | (k64 >> 4);
    int lane = ((row & 7) << 2) | ((kk >> 1) & 3);
    int reg  = ((row >> 3) & 1) | ((kk >> 3) << 1);
    return unit * 128 + lane * 4 + reg;
}
// B (16x8-k16 fragments): unit = (row>>3)*4 + (k64>>4); lane=((row&7)<<2)|((kk>>1)&3);
//   reg = kk>>3;  h2 = unit*64 + lane*2 + reg
__device__ __forceinline__ int b_h2(int row, int k64) {
    int kk = k64 & 15;
    int unit = ((row >> 3) << 2) | (k64 >> 4);
    int lane = ((row & 7) << 2) | ((kk >> 1) & 3);
    int reg  = kk >> 3;
    return unit * 64 + lane * 2 + reg;
}

// ---------------------------------------------------------------------------
// Kernel 1: expand x -> E (fp16, fragment-permuted). Block = 128 rows x 16
// features = 192 k-cols = exactly 3 BK=64 tiles. 512 threads, 4 evals each.
// ---------------------------------------------------------------------------
__global__ void expand_kernel(const float* __restrict__ x) {
    __shared__ __half2 st[3 * 4096];             // 3 tiles * 8192 halves = 48KB
    const int t  = threadIdx.x;
    const int mb = blockIdx.x >> 5;              // 64 row-blocks
    const int gg = blockIdx.x & 31;              // 32 groups of 16 features

    const float h = 2.0f / 14.0f;
    float g[15];
#pragma unroll
    for (int i = 0; i < 15; i++) g[i] = -1.0f + h * (float)i;

#pragma unroll
    for (int p = 0; p < 4; p++) {
        int q  = p * 512 + t;                    // 0..2047
        int bl = q >> 4;                         // row in block (0..127)
        int il = q & 15;                         // feature in group (0..15)
        float xv = x[(size_t)(mb * 128 + bl) * IN_F + gg * 16 + il];
        float xc = fminf(fmaxf(xv, -2.0f), 2.0f);

        float b[14];
#pragma unroll
        for (int s = 0; s < 14; s++) b[s] = (xc >= g[s] && xc < g[s + 1]) ? 1.0f : 0.0f;
#pragma unroll
        for (int k = 1; k <= 3; k++)
#pragma unroll
            for (int s = 0; s < 14 - k; s++) {
                float r1 = 1.0f / (g[s + k] - g[s]);
                float r2 = 1.0f / (g[s + k + 1] - g[s + 1]);
                b[s] = (xc - g[s]) * r1 * b[s] + (g[s + k + 1] - xc) * r2 * b[s + 1];
            }

        float v[12];
        v[0] = xv;                               // base path uses UNclipped x
#pragma unroll
        for (int j = 0; j < NBAS; j++) v[1 + j] = b[j];

        int kbase = il * 12;                     // even -> clean half2 pairs
#pragma unroll
        for (int jj = 0; jj < 6; jj++) {
            int k0  = kbase + 2 * jj;            // 0..190
            int kt  = k0 >> 6;
            int idx = kt * 4096 + a_h2(bl, k0 & 63);
            st[idx] = __floats2half2_rn(v[2 * jj], v[2 * jj + 1]);
        }
    }
    __syncthreads();

    // Coalesced copy-out: 12288 half2 = 3072 float4
    float4* dst = reinterpret_cast<float4*>(
        g_E + (size_t)mb * MBLK_HALVES + (size_t)gg * 3 * TILE_HALVES);
    const float4* src = reinterpret_cast<const float4*>(st);
#pragma unroll
    for (int r = 0; r < 6; r++) dst[t + r * 512] = src[t + r * 512];
}

// ---------------------------------------------------------------------------
// Kernel 2: pack weights -> W (fp16, fragment-permuted)
// ---------------------------------------------------------------------------
__global__ void pack_kernel(const float* __restrict__ bw, const float* __restrict__ sw) {
    int idx = blockIdx.x * blockDim.x + threadIdx.x;   // over OUT_F*IN_F
    if (idx >= OUT_F * IN_F) return;
    int o = idx >> 9, i = idx & 511;
    __half2* base = reinterpret_cast<__half2*>(
        g_W + (size_t)(o >> 7) * MBLK_HALVES);
    int ol = o & 127;

    float v[12];
    v[0] = bw[idx];
    const float* s = sw + (size_t)idx * NBAS;
#pragma unroll
    for (int j = 0; j < NBAS; j++) v[1 + j] = s[j];

    int kbase = i * 12;
#pragma unroll
    for (int jj = 0; jj < 6; jj++) {
        int k0 = kbase + 2 * jj;
        int kt = k0 >> 6;
        base[kt * 4096 + b_h2(ol, k0 & 63)] = __floats2half2_rn(v[2 * jj], v[2 * jj + 1]);
    }
}

// ---------------------------------------------------------------------------
// Kernel 3: fp16 mma.sync GEMM (m16n8k16), fragment-permuted operands.
// CTA 128x128, 8 warps (2x4), warp 64x32, BK=64, 3-stage cp.async.
// ---------------------------------------------------------------------------
__global__ void __launch_bounds__(256, 2) gemm_kernel(float* __restrict__ C) {
    extern __shared__ char dsm[];
    const int tid   = threadIdx.x;
    const int lane  = tid & 31;
    const int wid   = tid >> 5;
    const int mwarp = wid >> 2;        // 0..1
    const int nwarp = wid & 3;         // 0..3

    const char* Ab = reinterpret_cast<const char*>(g_E + (size_t)blockIdx.y * MBLK_HALVES);
    const char* Bb = reinterpret_cast<const char*>(g_W + (size_t)blockIdx.x * MBLK_HALVES);
    uint32_t sbase;
    asm("{ .reg .u64 t; cvta.to.shared.u64 t, %1; cvt.u32.u64 %0, t; }" : "=r"(sbase) : "l"(dsm));

    float acc[4][4][4];
#pragma unroll
    for (int i = 0; i < 4; i++)
#pragma unroll
        for (int j = 0; j < 4; j++)
#pragma unroll
            for (int k = 0; k < 4; k++) acc[i][j][k] = 0.0f;

    auto load_tile = [&](int kt, int s) {
        uint32_t sd = sbase + s * STAGE_B;
        const char* ga = Ab + (size_t)kt * TILE_B;
        const char* gb = Bb + (size_t)kt * TILE_B;
#pragma unroll
        for (int r = 0; r < 4; r++) {
            int q = tid + r * 256;                 // 0..1023 16B chunks per operand
            cp_async16(sd + q * 16, ga + q * 16);
            cp_async16(sd + TILE_B + q * 16, gb + q * 16);
        }
        asm volatile("cp.async.commit_group;\n");
    };

    load_tile(0, 0);
    load_tile(1, 1);

    int bufc = 0, bufl = 2;
#pragma unroll 1
    for (int kt = 0; kt < NKT; kt++) {
        asm volatile("cp.async.wait_group 1;\n" ::: "memory");
        __syncthreads();

        if (kt + 2 < NKT) load_tile(kt + 2, bufl);
        else asm volatile("cp.async.commit_group;\n");

        const char* sa = dsm + bufc * STAGE_B;
        const char* sb = sa + TILE_B;

#pragma unroll
        for (int kq = 0; kq < 4; kq++) {
            uint4 af[4];
            uint2 bf[4];
#pragma unroll
            for (int mi = 0; mi < 4; mi++)
                af[mi] = *reinterpret_cast<const uint4*>(
                    sa + (((mwarp * 4 + mi) * 4 + kq) * 512 + lane * 16));
#pragma unroll
            for (int ni = 0; ni < 4; ni++)
                bf[ni] = *reinterpret_cast<const uint2*>(
                    sb + (((nwarp * 4 + ni) * 4 + kq) * 256 + lane * 8));
#pragma unroll
            for (int mi = 0; mi < 4; mi++)
#pragma unroll
                for (int ni = 0; ni < 4; ni++)
                    asm volatile(
                        "mma.sync.aligned.m16n8k16.row.col.f32.f16.f16.f32 "
                        "{%0,%1,%2,%3}, {%4,%5,%6,%7}, {%8,%9}, {%0,%1,%2,%3};\n"
                        : "+f"(acc[mi][ni][0]), "+f"(acc[mi][ni][1]),
                          "+f"(acc[mi][ni][2]), "+f"(acc[mi][ni][3])
                        : "r"(af[mi].x), "r"(af[mi].y), "r"(af[mi].z), "r"(af[mi].w),
                          "r"(bf[ni].x), "r"(bf[ni].y));
        }

        bufc = (bufc == 2) ? 0 : bufc + 1;
        bufl = (bufl == 2) ? 0 : bufl + 1;
    }

    // ---- epilogue (fp32 accumulators, unchanged mapping) ----
    float* Cb = C + (size_t)blockIdx.y * 128 * OUT_F + blockIdx.x * 128;
    const int m0 = mwarp * 64, n0 = nwarp * 32;
#pragma unroll
    for (int mi = 0; mi < 4; mi++) {
#pragma unroll
        for (int ni = 0; ni < 4; ni++) {
            int r = m0 + mi * 16 + (lane >> 2);
            int c = n0 + ni * 8 + ((lane & 3) << 1);
            *reinterpret_cast<float2*>(Cb + (size_t)r * OUT_F + c) =
                make_float2(acc[mi][ni][0], acc[mi][ni][1]);
            *reinterpret_cast<float2*>(Cb + (size_t)(r + 8) * OUT_F + c) =
                make_float2(acc[mi][ni][2], acc[mi][ni][3]);
        }
    }
}

// ---------------------------------------------------------------------------
extern "C" void kernel_launch(void* const* d_in, const int* in_sizes, int n_in,
                              void* d_out, int out_size) {
    const float* x  = (const float*)d_in[0];   // (8192, 512)
    const float* bw = (const float*)d_in[1];   // (512, 512)
    const float* sw = (const float*)d_in[2];   // (512, 512, 11)
    float* out = (float*)d_out;                // (8192, 512)

    cudaFuncSetAttribute(gemm_kernel,
                         cudaFuncAttributeMaxDynamicSharedMemorySize, GEMM_SMEM);

    expand_kernel<<<64 * 32, 512>>>(x);
    pack_kernel<<<(OUT_F * IN_F + 255) / 256, 256>>>(bw, sw);
    gemm_kernel<<<dim3(OUT_F / 128, M_ROWS / 128), 256, GEMM_SMEM>>>(out);
}

// round 16
// speedup vs baseline: 2.8164x; 1.0783x over previous
#include <cuda_runtime.h>
#include <cuda_fp16.h>
#include <cstdint>

#define M_ROWS 8192
#define IN_F   512
#define OUT_F  512
#define NBAS   11
#define KDIM   6144                 // 512 * 12
#define BK     64
#define NKT    (KDIM / BK)          // 96
#define TILE_HALVES 8192            // 128 * 64
#define TILE_B  16384               // bytes per operand tile (fp16)
#define STAGE_B (2 * TILE_B)        // 32768
#define NSTAGE  3
#define GEMM_SMEM (NSTAGE * STAGE_B)   // 98304
#define MBLK_HALVES (128 * KDIM)    // 786432 halves per 128-row block

__device__ __half g_E[(size_t)M_ROWS * KDIM];   // A, m16n8k16-fragment-permuted
__device__ __half g_W[(size_t)OUT_F * KDIM];    // B, fragment-permuted

__device__ __forceinline__ void cp_async16(uint32_t saddr, const void* g) {
    asm volatile("cp.async.cg.shared.global [%0], [%1], 16;\n" :: "r"(saddr), "l"(g));
}

// half2-granule offset of element pair containing (row, k) inside one 128x64 tile
// (valid for any k: pair = floor(k/2), half position = k&1)
__device__ __forceinline__ int a_h2(int row, int k64) {
    int kk = k64 & 15;
    int unit = ((row >> 4) << 2) | (k64 >> 4);
    int lane = ((row & 7) << 2) | ((kk >> 1) & 3);
    int reg  = ((row >> 3) & 1) | ((kk >> 3) << 1);
    return unit * 128 + lane * 4 + reg;
}
__device__ __forceinline__ int b_h2(int row, int k64) {
    int kk = k64 & 15;
    int unit = ((row >> 3) << 2) | (k64 >> 4);
    int lane = ((row & 7) << 2) | ((kk >> 1) & 3);
    int reg  = kk >> 3;
    return unit * 64 + lane * 2 + reg;
}

// ---------------------------------------------------------------------------
// Kernel 1: expand x -> E (fp16, fragment-permuted), direct 4-basis evaluation.
// Block = 128 rows x 16 features = 192 k-cols = 3 BK=64 tiles. 512 thr, 4 evals.
// ---------------------------------------------------------------------------
__global__ void expand_kernel(const float* __restrict__ x) {
    __shared__ __half2 st[3 * 4096];             // 3 tiles * 8192 halves = 48KB
    __half* sth = reinterpret_cast<__half*>(st);
    const int t  = threadIdx.x;
    const int mb = blockIdx.x >> 5;              // 64 row-blocks
    const int gg = blockIdx.x & 31;              // 32 groups of 16 features

#pragma unroll
    for (int p = 0; p < 4; p++) {
        int q  = p * 512 + t;                    // 0..2047
        int bl = q >> 4;                         // row in block (0..127)
        int il = q & 15;                         // feature in group (0..15)
        float xv = x[(size_t)(mb * 128 + bl) * IN_F + gg * 16 + il];
        float xc = fminf(fmaxf(xv, -2.0f), 2.0f);

        const int kbase = il * 12;

        // Zero all 6 half2 slots for this (row, feature)
#pragma unroll
        for (int jj = 0; jj < 6; jj++) {
            int k0 = kbase + 2 * jj;
            st[(k0 >> 6) * 4096 + a_h2(bl, k0 & 63)] = __half2(__half(0.0f), __half(0.0f));
        }

        // Base path value (unclipped x) at k = kbase (even -> lo half)
        {
            int pr = (kbase >> 6) * 4096 + a_h2(bl, kbase & 63);
            sth[pr * 2] = __float2half(xv);
        }

        // Spline bases: nonzero only for xc in [-1, 1); interval j, local t in [0,1)
        float u = (xc + 1.0f) * 7.0f;
        float fj = floorf(u);
        int j = (int)fj;
        if (j >= 0 && j <= 13) {
            float tt = u - fj;
            float t2 = tt * tt, t3 = t2 * tt;
            const float s6 = 1.0f / 6.0f;
            float w[4];
            w[0] = (1.0f - tt); w[0] = w[0] * w[0] * w[0] * s6;      // s = j-3
            w[1] = (4.0f - 6.0f * t2 + 3.0f * t3) * s6;              // s = j-2
            w[2] = (1.0f + 3.0f * tt + 3.0f * t2 - 3.0f * t3) * s6;  // s = j-1
            w[3] = t3 * s6;                                          // s = j
#pragma unroll
            for (int d = 0; d < 4; d++) {
                int s = j - 3 + d;
                if (s >= 0 && s <= 10) {
                    int k  = kbase + 1 + s;
                    int pr = (k >> 6) * 4096 + a_h2(bl, k & 63);
                    sth[pr * 2 + (k & 1)] = __float2half(w[d]);
                }
            }
        }
    }
    __syncthreads();

    // Coalesced copy-out: 12288 half2 = 3072 float4
    float4* dst = reinterpret_cast<float4*>(
        g_E + (size_t)mb * MBLK_HALVES + (size_t)gg * 3 * TILE_HALVES);
    const float4* src = reinterpret_cast<const float4*>(st);
#pragma unroll
    for (int r = 0; r < 6; r++) dst[t + r * 512] = src[t + r * 512];
}

// ---------------------------------------------------------------------------
// Kernel 2: pack weights -> W (fp16, fragment-permuted)
// ---------------------------------------------------------------------------
__global__ void pack_kernel(const float* __restrict__ bw, const float* __restrict__ sw) {
    int idx = blockIdx.x * blockDim.x + threadIdx.x;   // over OUT_F*IN_F
    if (idx >= OUT_F * IN_F) return;
    int o = idx >> 9, i = idx & 511;
    __half2* base = reinterpret_cast<__half2*>(
        g_W + (size_t)(o >> 7) * MBLK_HALVES);
    int ol = o & 127;

    float v[12];
    v[0] = bw[idx];
    const float* s = sw + (size_t)idx * NBAS;
#pragma unroll
    for (int j = 0; j < NBAS; j++) v[1 + j] = s[j];

    int kbase = i * 12;
#pragma unroll
    for (int jj = 0; jj < 6; jj++) {
        int k0 = kbase + 2 * jj;
        int kt = k0 >> 6;
        base[kt * 4096 + b_h2(ol, k0 & 63)] = __floats2half2_rn(v[2 * jj], v[2 * jj + 1]);
    }
}

// ---------------------------------------------------------------------------
// Kernel 3: fp16 mma.sync GEMM (m16n8k16), fragment-permuted operands.
// CTA 128x128, 8 warps (2x4), warp 64x32, BK=64, 3-stage cp.async.
// ---------------------------------------------------------------------------
__global__ void __launch_bounds__(256, 2) gemm_kernel(float* __restrict__ C) {
    extern __shared__ char dsm[];
    const int tid   = threadIdx.x;
    const int lane  = tid & 31;
    const int wid   = tid >> 5;
    const int mwarp = wid >> 2;        // 0..1
    const int nwarp = wid & 3;         // 0..3

    const char* Ab = reinterpret_cast<const char*>(g_E + (size_t)blockIdx.y * MBLK_HALVES);
    const char* Bb = reinterpret_cast<const char*>(g_W + (size_t)blockIdx.x * MBLK_HALVES);
    uint32_t sbase;
    asm("{ .reg .u64 t; cvta.to.shared.u64 t, %1; cvt.u32.u64 %0, t; }" : "=r"(sbase) : "l"(dsm));

    float acc[4][4][4];
#pragma unroll
    for (int i = 0; i < 4; i++)
#pragma unroll
        for (int j = 0; j < 4; j++)
#pragma unroll
            for (int k = 0; k < 4; k++) acc[i][j][k] = 0.0f;

    auto load_tile = [&](int kt, int s) {
        uint32_t sd = sbase + s * STAGE_B;
        const char* ga = Ab + (size_t)kt * TILE_B;
        const char* gb = Bb + (size_t)kt * TILE_B;
#pragma unroll
        for (int r = 0; r < 4; r++) {
            int q = tid + r * 256;                 // 0..1023 16B chunks per operand
            cp_async16(sd + q * 16, ga + q * 16);
            cp_async16(sd + TILE_B + q * 16, gb + q * 16);
        }
        asm volatile("cp.async.commit_group;\n");
    };

    load_tile(0, 0);
    load_tile(1, 1);

    int bufc = 0, bufl = 2;
#pragma unroll 1
    for (int kt = 0; kt < NKT; kt++) {
        asm volatile("cp.async.wait_group 1;\n" ::: "memory");
        __syncthreads();

        if (kt + 2 < NKT) load_tile(kt + 2, bufl);
        else asm volatile("cp.async.commit_group;\n");

        const char* sa = dsm + bufc * STAGE_B;
        const char* sb = sa + TILE_B;

#pragma unroll
        for (int kq = 0; kq < 4; kq++) {
            uint4 af[4];
            uint2 bf[4];
#pragma unroll
            for (int mi = 0; mi < 4; mi++)
                af[mi] = *reinterpret_cast<const uint4*>(
                    sa + (((mwarp * 4 + mi) * 4 + kq) * 512 + lane * 16));
#pragma unroll
            for (int ni = 0; ni < 4; ni++)
                bf[ni] = *reinterpret_cast<const uint2*>(
                    sb + (((nwarp * 4 + ni) * 4 + kq) * 256 + lane * 8));
#pragma unroll
            for (int mi = 0; mi < 4; mi++)
#pragma unroll
                for (int ni = 0; ni < 4; ni++)
                    asm volatile(
                        "mma.sync.aligned.m16n8k16.row.col.f32.f16.f16.f32 "
                        "{%0,%1,%2,%3}, {%4,%5,%6,%7}, {%8,%9}, {%0,%1,%2,%3};\n"
                        : "+f"(acc[mi][ni][0]), "+f"(acc[mi][ni][1]),
                          "+f"(acc[mi][ni][2]), "+f"(acc[mi][ni][3])
                        : "r"(af[mi].x), "r"(af[mi].y), "r"(af[mi].z), "r"(af[mi].w),
                          "r"(bf[ni].x), "r"(bf[ni].y));
        }

        bufc = (bufc == 2) ? 0 : bufc + 1;
        bufl = (bufl == 2) ? 0 : bufl + 1;
    }

    // ---- epilogue (fp32 accumulators) ----
    float* Cb = C + (size_t)blockIdx.y * 128 * OUT_F + blockIdx.x * 128;
    const int m0 = mwarp * 64, n0 = nwarp * 32;
#pragma unroll
    for (int mi = 0; mi < 4; mi++) {
#pragma unroll
        for (int ni = 0; ni < 4; ni++) {
            int r = m0 + mi * 16 + (lane >> 2);
            int c = n0 + ni * 8 + ((lane & 3) << 1);
            *reinterpret_cast<float2*>(Cb + (size_t)r * OUT_F + c) =
                make_float2(acc[mi][ni][0], acc[mi][ni][1]);
            *reinterpret_cast<float2*>(Cb + (size_t)(r + 8) * OUT_F + c) =
                make_float2(acc[mi][ni][2], acc[mi][ni][3]);
        }
    }
}

// ---------------------------------------------------------------------------
extern "C" void kernel_launch(void* const* d_in, const int* in_sizes, int n_in,
                              void* d_out, int out_size) {
    const float* x  = (const float*)d_in[0];   // (8192, 512)
    const float* bw = (const float*)d_in[1];   // (512, 512)
    const float* sw = (const float*)d_in[2];   // (512, 512, 11)
    float* out = (float*)d_out;                // (8192, 512)

    cudaFuncSetAttribute(gemm_kernel,
                         cudaFuncAttributeMaxDynamicSharedMemorySize, GEMM_SMEM);

    expand_kernel<<<64 * 32, 512>>>(x);
    pack_kernel<<<(OUT_F * IN_F + 255) / 256, 256>>>(bw, sw);
    gemm_kernel<<<dim3(OUT_F / 128, M_ROWS / 128), 256, GEMM_SMEM>>>(out);
}